// round 3
// baseline (speedup 1.0000x reference)
#include <cuda_runtime.h>

#define B_DIM 8
#define C_DIM 4
#define T_DIM 262144
#define T4 (T_DIM / 4)

#define NTHREADS 256
#define ITERS 4
#define COLS_PER_BLOCK (64 * ITERS)            // 256 float4 columns per block
#define GRID_X (T4 / COLS_PER_BLOCK)           // 256
#define TOTAL_BLOCKS (GRID_X * B_DIM)          // 2048

// Scratch: per-batch 4x4 distance partial sums (index i*4+j; i = y ch, j = x ch)
// Zero-initialized at load; last block resets after each call -> deterministic replays.
__device__ float g_partial[B_DIM][16];
__device__ unsigned int g_ticket;

__global__ void __launch_bounds__(NTHREADS, 6) pit_fused_kernel(
    const float* __restrict__ x, const float* __restrict__ y,
    float* __restrict__ out) {
    const int tid  = threadIdx.x;
    const int lane = tid & 63;        // column offset within block (warp-coalesced)
    const int j    = tid >> 6;        // this thread's x channel (0..3)
    const int b    = blockIdx.y;

    const float4* __restrict__ xj =
        (const float4*)(x + (long long)b * C_DIM * T_DIM) + j * T4;
    const float4* __restrict__ y4 =
        (const float4*)(y + (long long)b * C_DIM * T_DIM);

    float acc0 = 0.f, acc1 = 0.f, acc2 = 0.f, acc3 = 0.f;

    const int base = blockIdx.x * COLS_PER_BLOCK + lane;
#pragma unroll
    for (int it = 0; it < ITERS; it++) {
        const int col = base + it * 64;
        const float4 xv = __ldcs(&xj[col]);       // read-once stream
        const float4 y0 = y4[0 * T4 + col];
        const float4 y1 = y4[1 * T4 + col];
        const float4 y2 = y4[2 * T4 + col];
        const float4 y3 = y4[3 * T4 + col];

        float d;
        d = xv.x - y0.x; acc0 += d * d;  d = xv.y - y0.y; acc0 += d * d;
        d = xv.z - y0.z; acc0 += d * d;  d = xv.w - y0.w; acc0 += d * d;
        d = xv.x - y1.x; acc1 += d * d;  d = xv.y - y1.y; acc1 += d * d;
        d = xv.z - y1.z; acc1 += d * d;  d = xv.w - y1.w; acc1 += d * d;
        d = xv.x - y2.x; acc2 += d * d;  d = xv.y - y2.y; acc2 += d * d;
        d = xv.z - y2.z; acc2 += d * d;  d = xv.w - y2.w; acc2 += d * d;
        d = xv.x - y3.x; acc3 += d * d;  d = xv.y - y3.y; acc3 += d * d;
        d = xv.z - y3.z; acc3 += d * d;  d = xv.w - y3.w; acc3 += d * d;
    }

    // Warp reduction (each warp has a single j; lanes are 32 distinct columns)
#pragma unroll
    for (int off = 16; off > 0; off >>= 1) {
        acc0 += __shfl_down_sync(0xffffffff, acc0, off);
        acc1 += __shfl_down_sync(0xffffffff, acc1, off);
        acc2 += __shfl_down_sync(0xffffffff, acc2, off);
        acc3 += __shfl_down_sync(0xffffffff, acc3, off);
    }

    __shared__ float s_acc[16];
    if (tid < 16) s_acc[tid] = 0.0f;
    __syncthreads();
    if ((tid & 31) == 0) {
        atomicAdd(&s_acc[0 * 4 + j], acc0);
        atomicAdd(&s_acc[1 * 4 + j], acc1);
        atomicAdd(&s_acc[2 * 4 + j], acc2);
        atomicAdd(&s_acc[3 * 4 + j], acc3);
    }
    __syncthreads();
    if (tid < 16) atomicAdd(&g_partial[b][tid], s_acc[tid]);

    // ---- last-block-done finalize ----
    __shared__ bool s_is_last;
    __threadfence();
    if (tid == 0) {
        unsigned int t = atomicAdd(&g_ticket, 1u);
        s_is_last = (t == TOTAL_BLOCKS - 1);
    }
    __syncthreads();
    if (!s_is_last) return;

    __shared__ float s_d[B_DIM * 16];
    if (tid < B_DIM * 16)
        s_d[tid] = __ldcg(&((const float*)g_partial)[tid]);
    __syncthreads();

    if (tid == 0) {
        const float inv_t = 1.0f / (float)T_DIM;
        float total = 0.0f;
        for (int bb = 0; bb < B_DIM; bb++) {
            const float* d = &s_d[bb * 16];
            float best = 3.4e38f;
            for (int p0 = 0; p0 < 4; p0++)
                for (int p1 = 0; p1 < 4; p1++) {
                    if (p1 == p0) continue;
                    for (int p2 = 0; p2 < 4; p2++) {
                        if (p2 == p0 || p2 == p1) continue;
                        int p3 = 6 - p0 - p1 - p2;
                        float c = d[0 * 4 + p0] + d[1 * 4 + p1] +
                                  d[2 * 4 + p2] + d[3 * 4 + p3];
                        best = fminf(best, c);
                    }
                }
            total += best * inv_t;
        }
        out[0] = total;
        g_ticket = 0;
    }
    if (tid < B_DIM * 16)
        ((float*)g_partial)[tid] = 0.0f;
}

extern "C" void kernel_launch(void* const* d_in, const int* in_sizes, int n_in,
                              void* d_out, int out_size) {
    const float* x = (const float*)d_in[0];
    const float* y = (const float*)d_in[1];
    float* out = (float*)d_out;

    dim3 grid(GRID_X, B_DIM);
    pit_fused_kernel<<<grid, NTHREADS>>>(x, y, out);
}